// round 13
// baseline (speedup 1.0000x reference)
#include <cuda_runtime.h>
#include <math.h>
#include <stdint.h>

#define XF      1024
#define NB      2048
#define G       16
#define C4      (XF / 4)       // 256 float4 columns per row

#define NSTATS   32            // stats blocks: each owns 8 float4-cols (one 128B line/row)
#define TB       256           // threads per block (both roles)
#define NBLK     (NSTATS + NB) // 2080 total blocks
#define RG       32            // row-groups per stats block (TB/8)
#define RPT      (NB / RG)     // 64 rows per stats thread

__device__ float4 g_mean4 [C4];
__device__ float4 g_scale4[C4];
__device__ float4 g_shift4[C4];
__device__ unsigned g_ready = 0;   // stats blocks done (0..NSTATS); reset each replay
__device__ unsigned g_done  = 0;   // blocks finished (0..NBLK);    reset each replay

__global__ void __launch_bounds__(TB) k_fused(const float* __restrict__ xf,
                                              const float* __restrict__ wp,
                                              float* __restrict__ out) {
    const int t = threadIdx.x;

    if (blockIdx.x < NSTATS) {
        // ───────────── stats role: block owns float4-cols [b*8, b*8+8) ─────────────
        const int b    = blockIdx.x;
        const int c    = t & 7;            // col within the 128B line
        const int rg   = t >> 3;           // 0..31 row group
        const int col4 = b * 8 + c;
        const float4* x4 = reinterpret_cast<const float4*>(xf);

        __shared__ float4 sA[TB];
        __shared__ float4 sB[TB];
        __shared__ float4 sMean[8];

        // Pass 1: column sums. Warp lanes cover 8 cols x 4 consecutive rows
        // -> 4 dense 128B lines per warp-load (vs 32 scattered in R9 layout).
        float4 a = make_float4(0.f, 0.f, 0.f, 0.f);
        #pragma unroll 8
        for (int i = 0; i < RPT; i++) {
            float4 x = x4[(size_t)(i * RG + rg) * C4 + col4];
            a.x += x.x; a.y += x.y; a.z += x.z; a.w += x.w;
        }
        sA[rg * 8 + c] = a;
        __syncthreads();
        #pragma unroll
        for (int s = RG / 2; s > 0; s >>= 1) {
            if (rg < s) {
                float4 o = sA[(rg + s) * 8 + c];
                sA[rg * 8 + c].x += o.x; sA[rg * 8 + c].y += o.y;
                sA[rg * 8 + c].z += o.z; sA[rg * 8 + c].w += o.w;
            }
            __syncthreads();
        }
        if (rg == 0) {
            float4 m = sA[c];
            const float inv = 1.0f / NB;
            m.x *= inv; m.y *= inv; m.z *= inv; m.w *= inv;
            sMean[c] = m;
        }
        __syncthreads();
        const float4 m = sMean[c];

        // Pass 2: relu stats (re-read; strip is L2-hot from pass 1)
        float4 s  = make_float4(0.f, 0.f, 0.f, 0.f);
        float4 ss = make_float4(0.f, 0.f, 0.f, 0.f);
        #pragma unroll 8
        for (int i = 0; i < RPT; i++) {
            float4 x = x4[(size_t)(i * RG + rg) * C4 + col4];
            float4 v;
            v.x = fmaxf(x.x - m.x, 0.f);
            v.y = fmaxf(x.y - m.y, 0.f);
            v.z = fmaxf(x.z - m.z, 0.f);
            v.w = fmaxf(x.w - m.w, 0.f);
            s.x += v.x;       s.y += v.y;       s.z += v.z;       s.w += v.w;
            ss.x += v.x*v.x;  ss.y += v.y*v.y;  ss.z += v.z*v.z;  ss.w += v.w*v.w;
        }
        sA[rg * 8 + c] = s;
        sB[rg * 8 + c] = ss;
        __syncthreads();
        #pragma unroll
        for (int sN = RG / 2; sN > 0; sN >>= 1) {
            if (rg < sN) {
                float4 oa = sA[(rg + sN) * 8 + c];
                float4 ob = sB[(rg + sN) * 8 + c];
                sA[rg * 8 + c].x += oa.x; sA[rg * 8 + c].y += oa.y;
                sA[rg * 8 + c].z += oa.z; sA[rg * 8 + c].w += oa.w;
                sB[rg * 8 + c].x += ob.x; sB[rg * 8 + c].y += ob.y;
                sB[rg * 8 + c].z += ob.z; sB[rg * 8 + c].w += ob.w;
            }
            __syncthreads();
        }

        if (rg == 0) {
            const float w = wp[0];
            float4 S = sA[c], SS = sB[c];
            const float invN = 1.0f / NB, invN1 = 1.0f / (NB - 1);
            float4 sc, sh;
            {
                float mu = S.x * invN;
                float var = (SS.x - (float)NB * mu * mu) * invN1;
                sc.x = w / sqrtf(var); sh.x = -mu * sc.x;
            }
            {
                float mu = S.y * invN;
                float var = (SS.y - (float)NB * mu * mu) * invN1;
                sc.y = w / sqrtf(var); sh.y = -mu * sc.y;
            }
            {
                float mu = S.z * invN;
                float var = (SS.z - (float)NB * mu * mu) * invN1;
                sc.z = w / sqrtf(var); sh.z = -mu * sc.z;
            }
            {
                float mu = S.w * invN;
                float var = (SS.w - (float)NB * mu * mu) * invN1;
                sc.w = w / sqrtf(var); sh.w = -mu * sc.w;
            }
            g_mean4 [col4] = m;
            g_scale4[col4] = sc;
            g_shift4[col4] = sh;
        }
        __syncthreads();
        if (t == 0) {
            __threadfence();                 // publish stats before signaling
            atomicAdd(&g_ready, 1u);
        }
    } else {
        // ───────────── writer role: one row per block ─────────────
        const int row = blockIdx.x - NSTATS;

        // independent prefetch: overlaps with stats blocks' work
        float4 x = reinterpret_cast<const float4*>(xf + (size_t)row * XF)[t];

        if (t == 0) {
            while (atomicAdd(&g_ready, 0u) < NSTATS) { }   // stats blocks are wave-1 resident: no deadlock
            __threadfence();                                // acquire
        }
        __syncthreads();

        float4 m  = g_mean4 [t];
        float4 sc = g_scale4[t];
        float4 sh = g_shift4[t];

        float4 v;
        v.x = fmaxf(x.x - m.x, 0.f) * sc.x + sh.x;
        v.y = fmaxf(x.y - m.y, 0.f) * sc.y + sh.y;
        v.z = fmaxf(x.z - m.z, 0.f) * sc.z + sh.z;
        v.w = fmaxf(x.w - m.w, 0.f) * sc.w + sh.w;

        float4* o = reinterpret_cast<float4*>(out + (size_t)row * XF * G) + t;
        #pragma unroll
        for (int g = 0; g < G; g++) {
            __stcs(o + g * C4, v);
        }
    }

    // graph-replay-safe reset: last finishing block zeroes both counters.
    __syncthreads();
    if (t == 0) {
        unsigned d = atomicAdd(&g_done, 1u);
        if (d == NBLK - 1) {
            atomicExch(&g_ready, 0u);
            atomicExch(&g_done,  0u);
        }
    }
}

extern "C" void kernel_launch(void* const* d_in, const int* in_sizes, int n_in,
                              void* d_out, int out_size) {
    const float* xf = (const float*)d_in[0];   // [2048, 1024] f32
    const float* wp = (const float*)d_in[1];   // [1] f32
    float* out = (float*)d_out;                // [2048, 16384] f32

    k_fused<<<NBLK, TB>>>(xf, wp, out);
}

// round 14
// speedup vs baseline: 1.8099x; 1.8099x over previous
#include <cuda_runtime.h>
#include <math.h>
#include <stdint.h>

#define XF      1024
#define NB      2048
#define G       16
#define C4      (XF / 4)       // 256 float4 columns per row

#define NSTATS   32            // stats blocks: each owns 8 float4-cols (one 128B line/row)
#define TB       256           // threads per block (both roles)
#define NBLK     (NSTATS + NB) // 2080 total blocks
#define RG       32            // row-groups per stats block (TB/8)
#define RPT      (NB / RG)     // 64 rows per stats thread
#define NFLAG    64            // distributed release flags (one 128B line each)

__device__ float4 g_mean4 [C4];
__device__ float4 g_scale4[C4];
__device__ float4 g_shift4[C4];
__device__ unsigned g_ready = 0;               // stats blocks done (only 32 atomics)
__device__ unsigned g_done  = 0;               // blocks finished; reset each replay
__device__ unsigned g_flag[NFLAG * 32];        // release flags, 128B apart (idx*32)

__global__ void __launch_bounds__(TB) k_fused(const float* __restrict__ xf,
                                              const float* __restrict__ wp,
                                              float* __restrict__ out) {
    const int t = threadIdx.x;

    if (blockIdx.x < NSTATS) {
        // ───────────── stats role: block owns float4-cols [b*8, b*8+8) ─────────────
        const int b    = blockIdx.x;
        const int c    = t & 7;            // col within the 128B line
        const int rg   = t >> 3;           // 0..31 row group
        const int col4 = b * 8 + c;
        const float4* x4 = reinterpret_cast<const float4*>(xf);

        __shared__ float4 sA[TB];
        __shared__ float4 sB[TB];
        __shared__ float4 sMean[8];
        __shared__ bool   sLast;

        // Pass 1: column sums (dense 128B-line access per warp)
        float4 a = make_float4(0.f, 0.f, 0.f, 0.f);
        #pragma unroll 8
        for (int i = 0; i < RPT; i++) {
            float4 x = x4[(size_t)(i * RG + rg) * C4 + col4];
            a.x += x.x; a.y += x.y; a.z += x.z; a.w += x.w;
        }
        sA[rg * 8 + c] = a;
        __syncthreads();
        #pragma unroll
        for (int s = RG / 2; s > 0; s >>= 1) {
            if (rg < s) {
                float4 o = sA[(rg + s) * 8 + c];
                sA[rg * 8 + c].x += o.x; sA[rg * 8 + c].y += o.y;
                sA[rg * 8 + c].z += o.z; sA[rg * 8 + c].w += o.w;
            }
            __syncthreads();
        }
        if (rg == 0) {
            float4 m = sA[c];
            const float inv = 1.0f / NB;
            m.x *= inv; m.y *= inv; m.z *= inv; m.w *= inv;
            sMean[c] = m;
        }
        __syncthreads();
        const float4 m = sMean[c];

        // Pass 2: relu stats (strip is L2-hot from pass 1)
        float4 s  = make_float4(0.f, 0.f, 0.f, 0.f);
        float4 ss = make_float4(0.f, 0.f, 0.f, 0.f);
        #pragma unroll 8
        for (int i = 0; i < RPT; i++) {
            float4 x = x4[(size_t)(i * RG + rg) * C4 + col4];
            float4 v;
            v.x = fmaxf(x.x - m.x, 0.f);
            v.y = fmaxf(x.y - m.y, 0.f);
            v.z = fmaxf(x.z - m.z, 0.f);
            v.w = fmaxf(x.w - m.w, 0.f);
            s.x += v.x;       s.y += v.y;       s.z += v.z;       s.w += v.w;
            ss.x += v.x*v.x;  ss.y += v.y*v.y;  ss.z += v.z*v.z;  ss.w += v.w*v.w;
        }
        sA[rg * 8 + c] = s;
        sB[rg * 8 + c] = ss;
        __syncthreads();
        #pragma unroll
        for (int sN = RG / 2; sN > 0; sN >>= 1) {
            if (rg < sN) {
                float4 oa = sA[(rg + sN) * 8 + c];
                float4 ob = sB[(rg + sN) * 8 + c];
                sA[rg * 8 + c].x += oa.x; sA[rg * 8 + c].y += oa.y;
                sA[rg * 8 + c].z += oa.z; sA[rg * 8 + c].w += oa.w;
                sB[rg * 8 + c].x += ob.x; sB[rg * 8 + c].y += ob.y;
                sB[rg * 8 + c].z += ob.z; sB[rg * 8 + c].w += ob.w;
            }
            __syncthreads();
        }

        if (rg == 0) {
            const float w = wp[0];
            float4 S = sA[c], SS = sB[c];
            const float invN = 1.0f / NB, invN1 = 1.0f / (NB - 1);
            float4 sc, sh;
            {
                float mu = S.x * invN;
                float var = (SS.x - (float)NB * mu * mu) * invN1;
                sc.x = w / sqrtf(var); sh.x = -mu * sc.x;
            }
            {
                float mu = S.y * invN;
                float var = (SS.y - (float)NB * mu * mu) * invN1;
                sc.y = w / sqrtf(var); sh.y = -mu * sc.y;
            }
            {
                float mu = S.z * invN;
                float var = (SS.z - (float)NB * mu * mu) * invN1;
                sc.z = w / sqrtf(var); sh.z = -mu * sc.z;
            }
            {
                float mu = S.w * invN;
                float var = (SS.w - (float)NB * mu * mu) * invN1;
                sc.w = w / sqrtf(var); sh.w = -mu * sc.w;
            }
            g_mean4 [col4] = m;
            g_scale4[col4] = sc;
            g_shift4[col4] = sh;
        }
        __syncthreads();

        // release: only 32 atomics total; last stats block fans out 64 flags
        if (t == 0) {
            __threadfence();                              // publish stats
            sLast = (atomicAdd(&g_ready, 1u) == NSTATS - 1);
        }
        __syncthreads();
        if (sLast && t < NFLAG) {
            __threadfence();
            g_flag[t * 32] = 1u;                          // one 128B line per flag
        }
    } else {
        // ───────────── writer role: one row per block ─────────────
        const int row = blockIdx.x - NSTATS;

        // independent prefetch: overlaps with the stats phase
        float4 x = reinterpret_cast<const float4*>(xf + (size_t)row * XF)[t];

        if (t == 0) {
            const unsigned* f = &g_flag[(blockIdx.x & (NFLAG - 1)) * 32];
            unsigned v;
            do {
                asm volatile("ld.global.cg.u32 %0, [%1];" : "=r"(v) : "l"(f));
                if (v) break;
                __nanosleep(200);
            } while (true);
            __threadfence();                              // acquire
        }
        __syncthreads();

        float4 m  = g_mean4 [t];
        float4 sc = g_scale4[t];
        float4 sh = g_shift4[t];

        float4 v;
        v.x = fmaxf(x.x - m.x, 0.f) * sc.x + sh.x;
        v.y = fmaxf(x.y - m.y, 0.f) * sc.y + sh.y;
        v.z = fmaxf(x.z - m.z, 0.f) * sc.z + sh.z;
        v.w = fmaxf(x.w - m.w, 0.f) * sc.w + sh.w;

        float4* o = reinterpret_cast<float4*>(out + (size_t)row * XF * G) + t;
        #pragma unroll
        for (int g = 0; g < G; g++) {
            __stcs(o + g * C4, v);
        }
    }

    // graph-replay-safe reset: last finishing block zeroes counters + flags.
    __syncthreads();
    if (t == 0) {
        unsigned d = atomicAdd(&g_done, 1u);
        if (d == NBLK - 1) {
            #pragma unroll
            for (int i = 0; i < NFLAG; i++) g_flag[i * 32] = 0u;
            atomicExch(&g_ready, 0u);
            __threadfence();
            atomicExch(&g_done,  0u);
        }
    }
}

extern "C" void kernel_launch(void* const* d_in, const int* in_sizes, int n_in,
                              void* d_out, int out_size) {
    const float* xf = (const float*)d_in[0];   // [2048, 1024] f32
    const float* wp = (const float*)d_in[1];   // [1] f32
    float* out = (float*)d_out;                // [2048, 16384] f32

    k_fused<<<NBLK, TB>>>(xf, wp, out);
}

// round 15
// speedup vs baseline: 2.1506x; 1.1882x over previous
#include <cuda_runtime.h>
#include <math.h>
#include <stdint.h>

#define XF      1024
#define NB      2048
#define G       16
#define C4      (XF / 4)        // 256 float4 columns per row

#define GS      128             // stats blocks
#define TS      512             // stats threads
#define RPT     8               // rows per stats thread

__device__ float4 g_mean4 [C4];
__device__ float4 g_scale4[C4];
__device__ float4 g_shift4[C4];

__device__ __forceinline__ void warp_bfly(float4& v) {
    // lanes hold (sub = lane>>1, c = lane&1); masks 2..16 reduce over sub, preserve c
    #pragma unroll
    for (int m = 2; m < 32; m <<= 1) {
        v.x += __shfl_xor_sync(0xffffffffu, v.x, m);
        v.y += __shfl_xor_sync(0xffffffffu, v.y, m);
        v.z += __shfl_xor_sync(0xffffffffu, v.z, m);
        v.w += __shfl_xor_sync(0xffffffffu, v.w, m);
    }
}

// ──────────────────────────────────────────────────────────────────────────
// K1: column-strip stats (R9 data layout, shuffle-based reductions).
// Block b owns float4-cols {2b, 2b+1} over the full batch; each thread's
// 8 rows live in registers across both phases. 3 __syncthreads total.
// ──────────────────────────────────────────────────────────────────────────
__global__ void __launch_bounds__(TS, 1) k_stats(const float* __restrict__ xf,
                                                 const float* __restrict__ wp) {
    const int t    = threadIdx.x;
    const int c    = t & 1;
    const int rg   = t >> 1;
    const int w    = t >> 5;
    const int lane = t & 31;
    const int col4 = blockIdx.x * 2 + c;
    const float4* x4 = reinterpret_cast<const float4*>(xf);

    __shared__ float4 sW [32];   // 16 warps x 2 cols
    __shared__ float4 sW2[32];
    __shared__ float4 sMean[2];

    // Phase 1: load 8 rows into registers, column partial sums
    float4 xv[RPT];
    float4 a = make_float4(0.f, 0.f, 0.f, 0.f);
    #pragma unroll
    for (int i = 0; i < RPT; i++) {
        xv[i] = x4[(size_t)(rg * RPT + i) * C4 + col4];
        a.x += xv[i].x; a.y += xv[i].y; a.z += xv[i].z; a.w += xv[i].w;
    }
    warp_bfly(a);                          // per-warp totals in lanes 0(c=0),1(c=1)
    if (lane < 2) sW[w * 2 + c] = a;
    __syncthreads();

    if (w == 0) {
        float4 v = sW[lane];               // lane = w'*2 + c'
        warp_bfly(v);                      // reduce over w'
        if (lane < 2) {
            const float inv = 1.0f / NB;
            v.x *= inv; v.y *= inv; v.z *= inv; v.w *= inv;
            sMean[lane] = v;
        }
    }
    __syncthreads();
    const float4 m = sMean[c];

    // Phase 2: relu stats from registers (no memory re-read)
    float4 s  = make_float4(0.f, 0.f, 0.f, 0.f);
    float4 ss = make_float4(0.f, 0.f, 0.f, 0.f);
    #pragma unroll
    for (int i = 0; i < RPT; i++) {
        float4 v;
        v.x = fmaxf(xv[i].x - m.x, 0.f);
        v.y = fmaxf(xv[i].y - m.y, 0.f);
        v.z = fmaxf(xv[i].z - m.z, 0.f);
        v.w = fmaxf(xv[i].w - m.w, 0.f);
        s.x += v.x;       s.y += v.y;       s.z += v.z;       s.w += v.w;
        ss.x += v.x*v.x;  ss.y += v.y*v.y;  ss.z += v.z*v.z;  ss.w += v.w*v.w;
    }
    warp_bfly(s);
    warp_bfly(ss);
    if (lane < 2) { sW[w * 2 + c] = s; sW2[w * 2 + c] = ss; }
    __syncthreads();

    if (w == 0) {
        float4 S  = sW [lane];
        float4 SS = sW2[lane];
        warp_bfly(S);
        warp_bfly(SS);
        if (lane < 2) {
            const int   myCol = blockIdx.x * 2 + lane;
            const float wv    = wp[0];
            const float invN  = 1.0f / NB, invN1 = 1.0f / (NB - 1);
            float4 sc, sh;
            {
                float mu = S.x * invN;
                float var = (SS.x - (float)NB * mu * mu) * invN1;
                sc.x = wv / sqrtf(var); sh.x = -mu * sc.x;
            }
            {
                float mu = S.y * invN;
                float var = (SS.y - (float)NB * mu * mu) * invN1;
                sc.y = wv / sqrtf(var); sh.y = -mu * sc.y;
            }
            {
                float mu = S.z * invN;
                float var = (SS.z - (float)NB * mu * mu) * invN1;
                sc.z = wv / sqrtf(var); sh.z = -mu * sc.z;
            }
            {
                float mu = S.w * invN;
                float var = (SS.w - (float)NB * mu * mu) * invN1;
                sc.w = wv / sqrtf(var); sh.w = -mu * sc.w;
            }
            g_mean4 [myCol] = sMean[lane];
            g_scale4[myCol] = sc;
            g_shift4[myCol] = sh;
        }
    }
}

// ──────────────────────────────────────────────────────────────────────────
// K2: write pass (R9/R12 structure) with DEFAULT stores: let the 126MB L2
// absorb the 134MB output at LTS speed; the DRAM drain overlaps the next
// replay's stats phase instead of serializing inside this kernel.
// ──────────────────────────────────────────────────────────────────────────
__global__ void __launch_bounds__(256) k_write(const float* __restrict__ xf,
                                               float* __restrict__ out) {
    const int row = blockIdx.x;
    const int t   = threadIdx.x;

    float4 x  = reinterpret_cast<const float4*>(xf + (size_t)row * XF)[t];
    float4 m  = g_mean4 [t];
    float4 sc = g_scale4[t];
    float4 sh = g_shift4[t];

    float4 v;
    v.x = fmaxf(x.x - m.x, 0.f) * sc.x + sh.x;
    v.y = fmaxf(x.y - m.y, 0.f) * sc.y + sh.y;
    v.z = fmaxf(x.z - m.z, 0.f) * sc.z + sh.z;
    v.w = fmaxf(x.w - m.w, 0.f) * sc.w + sh.w;

    float4* o = reinterpret_cast<float4*>(out + (size_t)row * XF * G) + t;
    #pragma unroll
    for (int g = 0; g < G; g++) {
        o[g * C4] = v;
    }
}

extern "C" void kernel_launch(void* const* d_in, const int* in_sizes, int n_in,
                              void* d_out, int out_size) {
    const float* xf = (const float*)d_in[0];   // [2048, 1024] f32
    const float* wp = (const float*)d_in[1];   // [1] f32
    float* out = (float*)d_out;                // [2048, 16384] f32

    k_stats<<<GS, TS>>>(xf, wp);
    k_write<<<NB, 256>>>(xf, out);
}

// round 16
// speedup vs baseline: 2.3205x; 1.0790x over previous
#include <cuda_runtime.h>
#include <math.h>
#include <stdint.h>

#define XF      1024
#define NB      2048
#define G       16
#define C4      (XF / 4)        // 256 float4 columns per row

// stats: 128 blocks x 1024 threads. Block b owns float4-cols {2b, 2b+1}.
// Thread t: c = t&1, rg = t>>1 (0..511), rows rg*4..rg*4+3 in registers.
#define GS      128
#define TS      1024
#define RPT     (NB / (TS / 2)) // 4 rows per thread

__device__ float4 g_mean4 [C4];
__device__ float4 g_scale4[C4];
__device__ float4 g_shift4[C4];

// ──────────────────────────────────────────────────────────────────────────
// K1: column-strip stats (R9 structure, 2x warps for latency hiding).
// Rows held in registers across both phases; smem tree reductions.
// ──────────────────────────────────────────────────────────────────────────
__global__ void __launch_bounds__(TS, 1) k_stats(const float* __restrict__ xf,
                                                 const float* __restrict__ wp) {
    const int t    = threadIdx.x;
    const int c    = t & 1;
    const int rg   = t >> 1;           // 0..511
    const int col4 = blockIdx.x * 2 + c;
    const float4* x4 = reinterpret_cast<const float4*>(xf);

    __shared__ float4 sA[TS];
    __shared__ float4 sB[TS];
    __shared__ float4 sMean[2];

    // Phase 1: load 4 rows (kept in registers), column partial sums
    float4 xv[RPT];
    float4 a = make_float4(0.f, 0.f, 0.f, 0.f);
    #pragma unroll
    for (int i = 0; i < RPT; i++) {
        xv[i] = x4[(size_t)(rg * RPT + i) * C4 + col4];
        a.x += xv[i].x; a.y += xv[i].y; a.z += xv[i].z; a.w += xv[i].w;
    }
    sA[t] = a;
    __syncthreads();

    // tree-reduce over rg (stride-2 layout: element = rg*2 + c)
    #pragma unroll
    for (int s = TS / 4; s > 0; s >>= 1) {
        if (rg < s) {
            float4 o = sA[(rg + s) * 2 + c];
            sA[t].x += o.x; sA[t].y += o.y; sA[t].z += o.z; sA[t].w += o.w;
        }
        __syncthreads();
    }
    if (rg == 0) {
        float4 m = sA[c];
        const float inv = 1.0f / NB;
        m.x *= inv; m.y *= inv; m.z *= inv; m.w *= inv;
        sMean[c] = m;
    }
    __syncthreads();
    const float4 m = sMean[c];

    // Phase 2: relu stats from registers (no memory re-read)
    float4 s  = make_float4(0.f, 0.f, 0.f, 0.f);
    float4 ss = make_float4(0.f, 0.f, 0.f, 0.f);
    #pragma unroll
    for (int i = 0; i < RPT; i++) {
        float4 v;
        v.x = fmaxf(xv[i].x - m.x, 0.f);
        v.y = fmaxf(xv[i].y - m.y, 0.f);
        v.z = fmaxf(xv[i].z - m.z, 0.f);
        v.w = fmaxf(xv[i].w - m.w, 0.f);
        s.x += v.x;       s.y += v.y;       s.z += v.z;       s.w += v.w;
        ss.x += v.x*v.x;  ss.y += v.y*v.y;  ss.z += v.z*v.z;  ss.w += v.w*v.w;
    }
    sA[t] = s;
    sB[t] = ss;
    __syncthreads();
    #pragma unroll
    for (int sN = TS / 4; sN > 0; sN >>= 1) {
        if (rg < sN) {
            float4 oa = sA[(rg + sN) * 2 + c];
            float4 ob = sB[(rg + sN) * 2 + c];
            sA[t].x += oa.x; sA[t].y += oa.y; sA[t].z += oa.z; sA[t].w += oa.w;
            sB[t].x += ob.x; sB[t].y += ob.y; sB[t].z += ob.z; sB[t].w += ob.w;
        }
        __syncthreads();
    }

    if (rg == 0) {
        const float w = wp[0];
        float4 S = sA[c], SS = sB[c];
        const float invN = 1.0f / NB, invN1 = 1.0f / (NB - 1);
        float4 sc, sh;
        {
            float mu = S.x * invN;
            float var = (SS.x - (float)NB * mu * mu) * invN1;
            sc.x = w / sqrtf(var); sh.x = -mu * sc.x;
        }
        {
            float mu = S.y * invN;
            float var = (SS.y - (float)NB * mu * mu) * invN1;
            sc.y = w / sqrtf(var); sh.y = -mu * sc.y;
        }
        {
            float mu = S.z * invN;
            float var = (SS.z - (float)NB * mu * mu) * invN1;
            sc.z = w / sqrtf(var); sh.z = -mu * sc.z;
        }
        {
            float mu = S.w * invN;
            float var = (SS.w - (float)NB * mu * mu) * invN1;
            sc.w = w / sqrtf(var); sh.w = -mu * sc.w;
        }
        g_mean4 [col4] = m;
        g_scale4[col4] = sc;
        g_shift4[col4] = sh;
    }
}

// ──────────────────────────────────────────────────────────────────────────
// K2: write pass — exact R12 winner. One block per row, 256 threads x float4;
// G=16 coalesced streaming stores (.cs keeps xf L2-resident across replays,
// which R15 showed matters for the stats kernel).
// ──────────────────────────────────────────────────────────────────────────
__global__ void __launch_bounds__(256) k_write(const float* __restrict__ xf,
                                               float* __restrict__ out) {
    const int row = blockIdx.x;
    const int t   = threadIdx.x;

    float4 x  = reinterpret_cast<const float4*>(xf + (size_t)row * XF)[t];
    float4 m  = g_mean4 [t];
    float4 sc = g_scale4[t];
    float4 sh = g_shift4[t];

    float4 v;
    v.x = fmaxf(x.x - m.x, 0.f) * sc.x + sh.x;
    v.y = fmaxf(x.y - m.y, 0.f) * sc.y + sh.y;
    v.z = fmaxf(x.z - m.z, 0.f) * sc.z + sh.z;
    v.w = fmaxf(x.w - m.w, 0.f) * sc.w + sh.w;

    float4* o = reinterpret_cast<float4*>(out + (size_t)row * XF * G) + t;
    #pragma unroll
    for (int g = 0; g < G; g++) {
        __stcs(o + g * C4, v);
    }
}

extern "C" void kernel_launch(void* const* d_in, const int* in_sizes, int n_in,
                              void* d_out, int out_size) {
    const float* xf = (const float*)d_in[0];   // [2048, 1024] f32
    const float* wp = (const float*)d_in[1];   // [1] f32
    float* out = (float*)d_out;                // [2048, 16384] f32

    k_stats<<<GS, TS>>>(xf, wp);
    k_write<<<NB, 256>>>(xf, out);
}